// round 9
// baseline (speedup 1.0000x reference)
#include <cuda_runtime.h>
#include <cuda_bf16.h>
#include <math.h>
#include <stdint.h>

// Problem constants (fixed shapes for this problem instance)
constexpr int NN    = 20000;           // nodes
constexpr int EE    = 100000;          // edges
constexpr int FIN   = 128;
constexpr int HID   = 610;
constexpr int HEADS = 4;
constexpr int HD    = HEADS * HID;     // 2440
constexpr int KER   = 50;
constexpr int C1    = HID - KER + 1;   // 561
constexpr int C2    = C1 - KER + 1;    // 512
constexpr int NOUT  = 86;

// ---------------- scratch (device globals; no allocation) ----------------
__device__ float Hg[(size_t)NN * HD];        // per-layer projected features [N,4,610]
__device__ float ASRCg[NN * HEADS];
__device__ float ADSTg[NN * HEADS];
__device__ float Mg[NN * HEADS];             // segment max
__device__ float DENg[NN * HEADS];           // segment sum
__device__ float ALPHAg[EE * HEADS];         // edge scores -> exp weights
__device__ float X1g[(size_t)NN * HID];      // layer-1 output (tf32-rounded)
__device__ float X2g[(size_t)NN * HID];      // layer-2 output (fp32, feeds conv)
__device__ float Y2g[(size_t)EE * C2];       // conv output [E,512] (tf32-rounded)
__device__ int   DEGg[NN];
__device__ int   ROWPTRg[NN + 1];
__device__ int   CURg[NN];
__device__ int   EIDXg[EE];
// tf32-preconverted GEMM operands
__device__ float XTg[(size_t)NN * FIN];
__device__ float W0Tg[(size_t)HD * FIN];
__device__ float W2Tg[(size_t)HD * HID];
__device__ float W8Tg[(size_t)NOUT * C2];

// ---------------- helpers ----------------
__device__ __forceinline__ void atomicMaxF(float* addr, float v) {
    if (v >= 0.f) atomicMax((int*)addr, __float_as_int(v));
    else          atomicMin((unsigned int*)addr, __float_as_uint(v));
}

__device__ __forceinline__ uint32_t f2tf32(float f) {
    uint32_t r;
    asm("cvt.rna.tf32.f32 %0, %1;" : "=r"(r) : "f"(f));
    return r;
}

__device__ __forceinline__ float roundtf(float f) {
    return __uint_as_float(f2tf32(f));
}

__device__ __forceinline__ uint32_t smem_u32(const void* p) {
    return (uint32_t)__cvta_generic_to_shared(p);
}

__device__ __forceinline__ void cp_async8(uint32_t dst, const void* src, int srcbytes) {
    asm volatile("cp.async.ca.shared.global [%0], [%1], 8, %2;"
                 :: "r"(dst), "l"(src), "r"(srcbytes));
}
__device__ __forceinline__ void cp_commit() {
    asm volatile("cp.async.commit_group;");
}
template <int NGroups>
__device__ __forceinline__ void cp_wait() {
    asm volatile("cp.async.wait_group %0;" :: "n"(NGroups));
}

// ---------------- pre-round elementwise: dst = tf32(src) ----------------
__global__ void k_cvt(const float* __restrict__ src, int n, int dsel) {
    float* dst = (dsel == 0) ? XTg : (dsel == 1) ? W0Tg : (dsel == 2) ? W2Tg : W8Tg;
    int i = blockIdx.x * blockDim.x + threadIdx.x;
    if (i < n) dst[i] = roundtf(src[i]);
}

// ---------------- pipelined tf32 GEMM: C[M,N] = A[M,K] * Bt[N,K]^T (+bias) -------------
// BM=BN=128, BK=32, 3-stage cp.async pipeline, 256 threads (8 warps),
// warp tile 64x32 via m16n8k8. smem rows stride 36 floats (conflict-free LDS.32).
// asel: 0=XTg 1=X1g 2=Y2g ; bsel: 0=W0Tg 1=W2Tg 2=W8Tg ; csel: 0=Hg 1=Copt.
constexpr int ROWF = 36;
constexpr int TILEF = 128 * ROWF;       // floats per tile (A or B) = 4608
constexpr int STAGEF = 2 * TILEF;       // floats per stage (A+B) = 9216
constexpr int NSTG = 3;
constexpr int GEMM_SMEM = NSTG * STAGEF * 4;  // 110592 bytes

__global__ __launch_bounds__(256, 2) void k_gemm_tf32p(const float* __restrict__ bias,
                                                       float* __restrict__ Copt,
                                                       int M, int N, int K,
                                                       int asel, int bsel, int csel) {
    const float* A  = (asel == 0) ? XTg  : (asel == 1) ? X1g  : Y2g;
    const float* Bt = (bsel == 0) ? W0Tg : (bsel == 1) ? W2Tg : W8Tg;
    float* C = csel ? Copt : Hg;

    extern __shared__ float dsm[];
    const uint32_t sbase = smem_u32(dsm);

    const int bm = blockIdx.y * 128;
    const int bn = blockIdx.x * 128;
    const int tid  = threadIdx.x;
    const int wid  = tid >> 5;
    const int lane = tid & 31;
    const int wm = (wid & 1) * 64;
    const int wn = (wid >> 1) * 32;
    const int lr = lane >> 2;             // 0..7
    const int lc = lane & 3;              // 0..3

    float acc[4][4][4];
#pragma unroll
    for (int mi = 0; mi < 4; mi++)
#pragma unroll
        for (int ni = 0; ni < 4; ni++)
#pragma unroll
            for (int q = 0; q < 4; q++) acc[mi][ni][q] = 0.f;

    const int nT = (K + 31) / 32;

    // ---- fill stage s with k-tile t (A and B, 8B cp.async chunks, zero-fill tails) ----
    auto fill = [&](int s, int t) {
        uint32_t sA = sbase + (uint32_t)(s * STAGEF) * 4u;
        uint32_t sB = sA + (uint32_t)TILEF * 4u;
        int k0 = t * 32;
#pragma unroll
        for (int i = 0; i < 8; i++) {
            int c = tid + i * 256;        // 0..2047
            int row = c >> 4;             // 0..127
            int kc  = c & 15;             // 8B chunk (2 floats)
            int gk = k0 + kc * 2;
            int rem = K - gk;
            int nbb = (rem >= 2) ? 8 : (rem == 1 ? 4 : 0);
            // A
            {
                int gr = bm + row;
                const float* src = A;
                int nb = 0;
                if (gr < M && nbb) { nb = nbb; src = A + (size_t)gr * K + gk; }
                cp_async8(sA + (uint32_t)(row * ROWF + kc * 2) * 4u, src, nb);
            }
            // B
            {
                int gr = bn + row;
                const float* src = Bt;
                int nb = 0;
                if (gr < N && nbb) { nb = nbb; src = Bt + (size_t)gr * K + gk; }
                cp_async8(sB + (uint32_t)(row * ROWF + kc * 2) * 4u, src, nb);
            }
        }
        cp_commit();
    };

    fill(0, 0);
    if (1 < nT) fill(1, 1); else cp_commit();

    int s = 0;                            // stage of tile t
    for (int t = 0; t < nT; t++) {
        // keep exactly 3 groups in flight so wait<2> always means "tile t resident"
        if (t + 2 < nT) {
            int s2 = s + 2; if (s2 >= NSTG) s2 -= NSTG;
            fill(s2, t + 2);
        } else {
            cp_commit();
        }
        cp_wait<2>();
        __syncthreads();

        const float* sA = dsm + s * STAGEF;
        const float* sB = sA + TILEF;

#pragma unroll
        for (int ks = 0; ks < 4; ks++) {
            const int k = ks * 8 + lc;
            uint32_t a[4][4];
#pragma unroll
            for (int mi = 0; mi < 4; mi++) {
                int r0 = wm + mi * 16 + lr;
                a[mi][0] = __float_as_uint(sA[r0 * ROWF + k]);
                a[mi][1] = __float_as_uint(sA[(r0 + 8) * ROWF + k]);
                a[mi][2] = __float_as_uint(sA[r0 * ROWF + k + 4]);
                a[mi][3] = __float_as_uint(sA[(r0 + 8) * ROWF + k + 4]);
            }
            uint32_t b[4][2];
#pragma unroll
            for (int ni = 0; ni < 4; ni++) {
                int rn = wn + ni * 8 + lr;
                b[ni][0] = __float_as_uint(sB[rn * ROWF + k]);
                b[ni][1] = __float_as_uint(sB[rn * ROWF + k + 4]);
            }
#pragma unroll
            for (int mi = 0; mi < 4; mi++)
#pragma unroll
                for (int ni = 0; ni < 4; ni++) {
                    asm volatile(
                        "mma.sync.aligned.m16n8k8.row.col.f32.tf32.tf32.f32 "
                        "{%0,%1,%2,%3}, {%4,%5,%6,%7}, {%8,%9}, {%0,%1,%2,%3};"
                        : "+f"(acc[mi][ni][0]), "+f"(acc[mi][ni][1]),
                          "+f"(acc[mi][ni][2]), "+f"(acc[mi][ni][3])
                        : "r"(a[mi][0]), "r"(a[mi][1]), "r"(a[mi][2]), "r"(a[mi][3]),
                          "r"(b[ni][0]), "r"(b[ni][1]));
                }
        }
        __syncthreads();
        if (++s >= NSTG) s = 0;
    }

    // epilogue
#pragma unroll
    for (int mi = 0; mi < 4; mi++) {
        int r0 = bm + wm + mi * 16 + lr;
#pragma unroll
        for (int ni = 0; ni < 4; ni++) {
            int c0 = bn + wn + ni * 8 + 2 * lc;
#pragma unroll
            for (int half = 0; half < 2; half++) {
                int gr = r0 + half * 8;
                if (gr >= M) continue;
                float v0 = acc[mi][ni][half * 2 + 0];
                float v1 = acc[mi][ni][half * 2 + 1];
                if (c0 < N) {
                    float o = v0 + (bias ? bias[c0] : 0.f);
                    C[(size_t)gr * N + c0] = o;
                }
                if (c0 + 1 < N) {
                    float o = v1 + (bias ? bias[c0 + 1] : 0.f);
                    C[(size_t)gr * N + c0 + 1] = o;
                }
            }
        }
    }
}

// ---------------- attention scores ----------------
__global__ void k_scores(const float* __restrict__ att_s, const float* __restrict__ att_d) {
    int n = blockIdx.x;
    int h = threadIdx.y;
    int lane = threadIdx.x;
    const float* hp = Hg + (size_t)n * HD + h * HID;
    const float* as = att_s + h * HID;
    const float* ad = att_d + h * HID;
    float s1 = 0.f, s2 = 0.f;
    for (int d = lane; d < HID; d += 32) {
        float v = hp[d];
        s1 += v * as[d];
        s2 += v * ad[d];
    }
#pragma unroll
    for (int o = 16; o; o >>= 1) {
        s1 += __shfl_down_sync(0xffffffffu, s1, o);
        s2 += __shfl_down_sync(0xffffffffu, s2, o);
    }
    if (lane == 0) {
        ASRCg[n * HEADS + h] = s1;
        ADSTg[n * HEADS + h] = s2;
    }
}

__global__ void k_init_md() {
    int i = blockIdx.x * blockDim.x + threadIdx.x;
    if (i < NN * HEADS) { Mg[i] = -INFINITY; DENg[i] = 0.f; }
}

__global__ void k_alpha(const int* __restrict__ ei) {
    int i = blockIdx.x * blockDim.x + threadIdx.x;
    if (i >= EE * HEADS) return;
    int e = i >> 2, h = i & 3;
    int s = ei[e];
    int d = ei[EE + e];
    float a = ASRCg[s * 4 + h] + ADSTg[d * 4 + h];
    a = (a > 0.f) ? a : 0.2f * a;      // leaky relu 0.2
    ALPHAg[i] = a;
    atomicMaxF(&Mg[d * 4 + h], a);
}

__global__ void k_expsum(const int* __restrict__ ei) {
    int i = blockIdx.x * blockDim.x + threadIdx.x;
    if (i >= EE * HEADS) return;
    int e = i >> 2, h = i & 3;
    int d = ei[EE + e];
    float w = expf(ALPHAg[i] - Mg[d * 4 + h]);
    ALPHAg[i] = w;
    atomicAdd(&DENg[d * 4 + h], w);
}

// ---------------- CSR build (by dst) ----------------
__global__ void k_zero_deg() {
    int i = blockIdx.x * blockDim.x + threadIdx.x;
    if (i < NN) DEGg[i] = 0;
}
__global__ void k_hist(const int* __restrict__ ei) {
    int e = blockIdx.x * blockDim.x + threadIdx.x;
    if (e < EE) atomicAdd(&DEGg[ei[EE + e]], 1);
}
__global__ void k_scan() {  // single block, 1024 threads
    __shared__ int sh[1024];
    __shared__ int carry;
    int tid = threadIdx.x;
    if (tid == 0) carry = 0;
    __syncthreads();
    for (int base = 0; base < NN; base += 1024) {
        int i = base + tid;
        int v = (i < NN) ? DEGg[i] : 0;
        sh[tid] = v;
        __syncthreads();
        for (int off = 1; off < 1024; off <<= 1) {
            int t = (tid >= off) ? sh[tid - off] : 0;
            __syncthreads();
            sh[tid] += t;
            __syncthreads();
        }
        int c = carry;
        if (i < NN) ROWPTRg[i + 1] = c + sh[tid];
        __syncthreads();
        if (tid == 1023) carry = c + sh[1023];
        __syncthreads();
    }
    if (tid == 0) ROWPTRg[0] = 0;
}
__global__ void k_curcopy() {
    int i = blockIdx.x * blockDim.x + threadIdx.x;
    if (i < NN) CURg[i] = ROWPTRg[i];
}
__global__ void k_fill(const int* __restrict__ ei) {
    int e = blockIdx.x * blockDim.x + threadIdx.x;
    if (e < EE) {
        int d = ei[EE + e];
        int p = atomicAdd(&CURg[d], 1);
        EIDXg[p] = e;
    }
}

// ---------------- pull-style softmax-weighted aggregation + head-mean + bias + relu --------
__global__ __launch_bounds__(256) void k_aggregate(const int* __restrict__ ei,
                                                   const float* __restrict__ bias,
                                                   int layer2) {
    int n = blockIdx.x;
    int tid = threadIdx.x;
    float r[3][4];
#pragma unroll
    for (int a = 0; a < 3; a++)
#pragma unroll
        for (int b = 0; b < 4; b++) r[a][b] = 0.f;
    float dinv[4];
#pragma unroll
    for (int h = 0; h < 4; h++) dinv[h] = 1.f / (DENg[n * 4 + h] + 1e-16f);
    int beg = ROWPTRg[n], end = ROWPTRg[n + 1];
    for (int t = beg; t < end; t++) {
        int e = EIDXg[t];
        int s = ei[e];
        const float* hp = Hg + (size_t)s * HD;
        float a0 = ALPHAg[4 * e + 0] * dinv[0];
        float a1 = ALPHAg[4 * e + 1] * dinv[1];
        float a2 = ALPHAg[4 * e + 2] * dinv[2];
        float a3 = ALPHAg[4 * e + 3] * dinv[3];
#pragma unroll
        for (int jj = 0; jj < 3; jj++) {
            int j = tid + jj * 256;
            if (j < HID) {
                r[jj][0] += hp[j] * a0;
                r[jj][1] += hp[j + HID] * a1;
                r[jj][2] += hp[j + 2 * HID] * a2;
                r[jj][3] += hp[j + 3 * HID] * a3;
            }
        }
    }
    float* xo = layer2 ? X2g : X1g;
#pragma unroll
    for (int jj = 0; jj < 3; jj++) {
        int j = tid + jj * 256;
        if (j < HID) {
            float v = (r[jj][0] + r[jj][1] + r[jj][2] + r[jj][3]) * 0.25f + bias[j];
            v = v > 0.f ? v : 0.f;
            xo[(size_t)n * HID + j] = layer2 ? v : roundtf(v);
        }
    }
}

// ---------------- fused edge conv: (2x50 conv -> relu) -> (50 conv -> relu) ----------------
__global__ __launch_bounds__(128) void k_conv(const int* __restrict__ ei,
                                              const float* __restrict__ w4,
                                              const float* __restrict__ b4,
                                              const float* __restrict__ w6,
                                              const float* __restrict__ b6) {
    int e = blockIdx.x;
    __shared__ float xs[616], xd[616];
    __shared__ float y1[C1];
    __shared__ float c0[KER], c1[KER], c2[KER];
    int tid = threadIdx.x;
    int s = ei[e];
    int d = ei[EE + e];
    for (int j = tid; j < 616; j += 128) {
        xs[j] = (j < HID) ? X2g[(size_t)s * HID + j] : 0.f;
        xd[j] = (j < HID) ? X2g[(size_t)d * HID + j] : 0.f;
    }
    if (tid < KER) { c0[tid] = w4[tid]; c1[tid] = w4[KER + tid]; c2[tid] = w6[tid]; }
    __syncthreads();

    // conv1: 5 outputs/thread, register sliding window
    float bb4 = b4[0];
    int j0 = tid * 5;
    if (j0 < C1) {
        float acc[5] = {bb4, bb4, bb4, bb4, bb4};
        float ws[5], wd[5];
#pragma unroll
        for (int i = 0; i < 5; i++) { ws[i] = xs[j0 + i]; wd[i] = xd[j0 + i]; }
#pragma unroll
        for (int k = 0; k < KER; k++) {
            float u0 = c0[k], u1 = c1[k];
#pragma unroll
            for (int i = 0; i < 5; i++) acc[i] += ws[i] * u0 + wd[i] * u1;
            if (k < KER - 1) {
#pragma unroll
                for (int i = 0; i < 4; i++) { ws[i] = ws[i + 1]; wd[i] = wd[i + 1]; }
                ws[4] = xs[j0 + k + 5];
                wd[4] = xd[j0 + k + 5];
            }
        }
#pragma unroll
        for (int i = 0; i < 5; i++) {
            int j = j0 + i;
            if (j < C1) y1[j] = acc[i] > 0.f ? acc[i] : 0.f;
        }
    }
    __syncthreads();

    // conv2: 4 outputs/thread (128*4 = 512 exactly); output tf32-rounded for final GEMM
    float bb6 = b6[0];
    int j2 = tid * 4;
    float acc2[4] = {bb6, bb6, bb6, bb6};
    float wy[4];
#pragma unroll
    for (int i = 0; i < 4; i++) wy[i] = y1[j2 + i];
#pragma unroll
    for (int k = 0; k < KER; k++) {
        float u = c2[k];
#pragma unroll
        for (int i = 0; i < 4; i++) acc2[i] += wy[i] * u;
        if (k < KER - 1) {
#pragma unroll
            for (int i = 0; i < 3; i++) wy[i] = wy[i + 1];
            wy[3] = y1[j2 + k + 4];
        }
    }
    float4 o;
    o.x = roundtf(acc2[0] > 0.f ? acc2[0] : 0.f);
    o.y = roundtf(acc2[1] > 0.f ? acc2[1] : 0.f);
    o.z = roundtf(acc2[2] > 0.f ? acc2[2] : 0.f);
    o.w = roundtf(acc2[3] > 0.f ? acc2[3] : 0.f);
    *reinterpret_cast<float4*>(&Y2g[(size_t)e * C2 + j2]) = o;
}

// ---------------- host launcher ----------------
extern "C" void kernel_launch(void* const* d_in, const int* in_sizes, int n_in,
                              void* d_out, int out_size) {
    const float* x   = (const float*)d_in[0];
    const int*   ei  = (const int*)d_in[1];
    const float* w0  = (const float*)d_in[2];
    const float* b0  = (const float*)d_in[3];
    const float* as0 = (const float*)d_in[4];
    const float* ad0 = (const float*)d_in[5];
    const float* w2  = (const float*)d_in[6];
    const float* b2  = (const float*)d_in[7];
    const float* as1 = (const float*)d_in[8];
    const float* ad1 = (const float*)d_in[9];
    const float* w4  = (const float*)d_in[10];
    const float* b4  = (const float*)d_in[11];
    const float* w6  = (const float*)d_in[12];
    const float* b6  = (const float*)d_in[13];
    const float* w8  = (const float*)d_in[14];
    const float* b8  = (const float*)d_in[15];
    float* out = (float*)d_out;

    cudaFuncSetAttribute(k_gemm_tf32p, cudaFuncAttributeMaxDynamicSharedMemorySize, GEMM_SMEM);

    // --- pre-round GEMM operands to tf32 ---
    k_cvt<<<(NN * FIN + 255) / 256, 256>>>(x, NN * FIN, 0);
    k_cvt<<<(HD * FIN + 255) / 256, 256>>>(w0, HD * FIN, 1);
    k_cvt<<<(HD * HID + 255) / 256, 256>>>(w2, HD * HID, 2);
    k_cvt<<<(NOUT * C2 + 255) / 256, 256>>>(w8, NOUT * C2, 3);

    // --- CSR by dst (reused by both layers) ---
    k_zero_deg<<<(NN + 255) / 256, 256>>>();
    k_hist<<<(EE + 255) / 256, 256>>>(ei);
    k_scan<<<1, 1024>>>();
    k_curcopy<<<(NN + 255) / 256, 256>>>();
    k_fill<<<(EE + 255) / 256, 256>>>(ei);

    dim3 bScores(32, 4);
    int gEH = (EE * HEADS + 255) / 256;
    int gMD = (NN * HEADS + 255) / 256;

    dim3 gH((HD + 127) / 128, (NN + 127) / 128);

    // --- GAT layer 1 ---
    k_gemm_tf32p<<<gH, 256, GEMM_SMEM>>>(nullptr, nullptr, NN, HD, FIN, 0, 0, 0);
    k_scores<<<NN, bScores>>>(as0, ad0);
    k_init_md<<<gMD, 256>>>();
    k_alpha<<<gEH, 256>>>(ei);
    k_expsum<<<gEH, 256>>>(ei);
    k_aggregate<<<NN, 256>>>(ei, b0, 0);

    // --- GAT layer 2 ---
    k_gemm_tf32p<<<gH, 256, GEMM_SMEM>>>(nullptr, nullptr, NN, HD, HID, 1, 1, 0);
    k_scores<<<NN, bScores>>>(as1, ad1);
    k_init_md<<<gMD, 256>>>();
    k_alpha<<<gEH, 256>>>(ei);
    k_expsum<<<gEH, 256>>>(ei);
    k_aggregate<<<NN, 256>>>(ei, b2, 1);

    // --- fused edge convs ---
    k_conv<<<EE, 128>>>(ei, w4, b4, w6, b6);

    // --- final linear [E,512] x [512,86]^T + b8 ---
    dim3 gO((NOUT + 127) / 128, (EE + 127) / 128);
    k_gemm_tf32p<<<gO, 256, GEMM_SMEM>>>(b8, out, EE, NOUT, C2, 2, 2, 1);
}

// round 10
// speedup vs baseline: 1.5414x; 1.5414x over previous
#include <cuda_runtime.h>
#include <cuda_bf16.h>
#include <math.h>
#include <stdint.h>

// Problem constants (fixed shapes for this problem instance)
constexpr int NN    = 20000;           // nodes
constexpr int EE    = 100000;          // edges
constexpr int FIN   = 128;
constexpr int HID   = 610;
constexpr int HEADS = 4;
constexpr int HD    = HEADS * HID;     // 2440
constexpr int KER   = 50;
constexpr int C1    = HID - KER + 1;   // 561
constexpr int C2    = C1 - KER + 1;    // 512
constexpr int NOUT  = 86;

// ---------------- scratch (device globals; no allocation) ----------------
__device__ float Hg[(size_t)NN * HD];        // per-layer projected features [N,4,610]
__device__ float ASRCg[NN * HEADS];
__device__ float ADSTg[NN * HEADS];
__device__ float X1g[(size_t)NN * HID];      // layer-1 output (tf32-rounded)
__device__ float X2g[(size_t)NN * HID];      // layer-2 output (fp32, feeds conv)
__device__ float Y2g[(size_t)EE * C2];       // conv output [E,512] (tf32-rounded)
__device__ int   DEGg[NN];
__device__ int   ROWPTRg[NN + 1];
__device__ int   CURg[NN];
__device__ int   EIDXg[EE];
// tf32-preconverted GEMM operands
__device__ float XTg[(size_t)NN * FIN];
__device__ float W0Tg[(size_t)HD * FIN];
__device__ float W2Tg[(size_t)HD * HID];
__device__ float W8Tg[(size_t)NOUT * C2];

// ---------------- helpers ----------------
__device__ __forceinline__ uint32_t f2tf32(float f) {
    uint32_t r;
    asm("cvt.rna.tf32.f32 %0, %1;" : "=r"(r) : "f"(f));
    return r;
}

__device__ __forceinline__ float roundtf(float f) {
    return __uint_as_float(f2tf32(f));
}

__device__ __forceinline__ uint32_t smem_u32(const void* p) {
    return (uint32_t)__cvta_generic_to_shared(p);
}

__device__ __forceinline__ void cp_async8(uint32_t dst, const void* src, int srcbytes) {
    asm volatile("cp.async.ca.shared.global [%0], [%1], 8, %2;"
                 :: "r"(dst), "l"(src), "r"(srcbytes));
}
__device__ __forceinline__ void cp_commit() {
    asm volatile("cp.async.commit_group;");
}
template <int NGroups>
__device__ __forceinline__ void cp_wait() {
    asm volatile("cp.async.wait_group %0;" :: "n"(NGroups));
}

// ---------------- pre-round elementwise: dst = tf32(src) ----------------
__global__ void k_cvt(const float* __restrict__ src, int n, int dsel) {
    float* dst = (dsel == 0) ? XTg : (dsel == 1) ? W0Tg : (dsel == 2) ? W2Tg : W8Tg;
    int i = blockIdx.x * blockDim.x + threadIdx.x;
    if (i < n) dst[i] = roundtf(src[i]);
}

// ---------------- pipelined tf32 GEMM: C[M,N] = A[M,K] * Bt[N,K]^T (+bias) -------------
// Round-7 proven config: BM=BN=128, BK=32, 2-stage cp.async double buffer,
// 256 threads (8 warps), warp tile 64x32 via m16n8k8, ROWF=36 conflict-free LDS.32.
// asel: 0=XTg 1=X1g 2=Y2g ; bsel: 0=W0Tg 1=W2Tg 2=W8Tg ; csel: 0=Hg 1=Copt.
constexpr int ROWF = 36;
constexpr int TILEF = 128 * ROWF;       // floats per tile (A or B)
constexpr int STAGEF = 2 * TILEF;       // floats per stage (A+B)
constexpr int GEMM_SMEM = 2 * STAGEF * 4;  // bytes = 73728

__global__ __launch_bounds__(256, 2) void k_gemm_tf32p(const float* __restrict__ bias,
                                                       float* __restrict__ Copt,
                                                       int M, int N, int K,
                                                       int asel, int bsel, int csel) {
    const float* A  = (asel == 0) ? XTg  : (asel == 1) ? X1g  : Y2g;
    const float* Bt = (bsel == 0) ? W0Tg : (bsel == 1) ? W2Tg : W8Tg;
    float* C = csel ? Copt : Hg;

    extern __shared__ float dsm[];
    const uint32_t sbase = smem_u32(dsm);

    const int bm = blockIdx.y * 128;
    const int bn = blockIdx.x * 128;
    const int tid  = threadIdx.x;
    const int wid  = tid >> 5;
    const int lane = tid & 31;
    const int wm = (wid & 1) * 64;
    const int wn = (wid >> 1) * 32;
    const int lr = lane >> 2;             // 0..7
    const int lc = lane & 3;              // 0..3

    float acc[4][4][4];
#pragma unroll
    for (int mi = 0; mi < 4; mi++)
#pragma unroll
        for (int ni = 0; ni < 4; ni++)
#pragma unroll
            for (int q = 0; q < 4; q++) acc[mi][ni][q] = 0.f;

    const int nT = (K + 31) / 32;

    // ---- fill stage s with k-tile k0 (A and B, 8B cp.async chunks) ----
    auto fill = [&](int s, int k0) {
        uint32_t sA = sbase + (uint32_t)(s * STAGEF) * 4u;
        uint32_t sB = sA + (uint32_t)TILEF * 4u;
#pragma unroll
        for (int i = 0; i < 8; i++) {
            int c = tid + i * 256;        // 0..2047
            int row = c >> 4;             // 0..127
            int kc  = c & 15;             // 8B chunk (2 floats)
            int gk = k0 + kc * 2;
            int rem = K - gk;
            int nbb = (rem >= 2) ? 8 : (rem == 1 ? 4 : 0);
            // A
            {
                int gr = bm + row;
                const float* src = A;
                int nb = 0;
                if (gr < M && nbb) { nb = nbb; src = A + (size_t)gr * K + gk; }
                cp_async8(sA + (uint32_t)(row * ROWF + kc * 2) * 4u, src, nb);
            }
            // B
            {
                int gr = bn + row;
                const float* src = Bt;
                int nb = 0;
                if (gr < N && nbb) { nb = nbb; src = Bt + (size_t)gr * K + gk; }
                cp_async8(sB + (uint32_t)(row * ROWF + kc * 2) * 4u, src, nb);
            }
        }
        cp_commit();
    };

    fill(0, 0);

    for (int t = 0; t < nT; t++) {
        if (t + 1 < nT) {
            fill((t + 1) & 1, (t + 1) * 32);
            cp_wait<1>();
        } else {
            cp_wait<0>();
        }
        __syncthreads();

        const float* sA = dsm + (t & 1) * STAGEF;
        const float* sB = sA + TILEF;

#pragma unroll
        for (int ks = 0; ks < 4; ks++) {
            const int k = ks * 8 + lc;
            uint32_t a[4][4];
#pragma unroll
            for (int mi = 0; mi < 4; mi++) {
                int r0 = wm + mi * 16 + lr;
                a[mi][0] = __float_as_uint(sA[r0 * ROWF + k]);
                a[mi][1] = __float_as_uint(sA[(r0 + 8) * ROWF + k]);
                a[mi][2] = __float_as_uint(sA[r0 * ROWF + k + 4]);
                a[mi][3] = __float_as_uint(sA[(r0 + 8) * ROWF + k + 4]);
            }
            uint32_t b[4][2];
#pragma unroll
            for (int ni = 0; ni < 4; ni++) {
                int rn = wn + ni * 8 + lr;
                b[ni][0] = __float_as_uint(sB[rn * ROWF + k]);
                b[ni][1] = __float_as_uint(sB[rn * ROWF + k + 4]);
            }
#pragma unroll
            for (int mi = 0; mi < 4; mi++)
#pragma unroll
                for (int ni = 0; ni < 4; ni++) {
                    asm volatile(
                        "mma.sync.aligned.m16n8k8.row.col.f32.tf32.tf32.f32 "
                        "{%0,%1,%2,%3}, {%4,%5,%6,%7}, {%8,%9}, {%0,%1,%2,%3};"
                        : "+f"(acc[mi][ni][0]), "+f"(acc[mi][ni][1]),
                          "+f"(acc[mi][ni][2]), "+f"(acc[mi][ni][3])
                        : "r"(a[mi][0]), "r"(a[mi][1]), "r"(a[mi][2]), "r"(a[mi][3]),
                          "r"(b[ni][0]), "r"(b[ni][1]));
                }
        }
        __syncthreads();
    }

    // epilogue
#pragma unroll
    for (int mi = 0; mi < 4; mi++) {
        int r0 = bm + wm + mi * 16 + lr;
#pragma unroll
        for (int ni = 0; ni < 4; ni++) {
            int c0 = bn + wn + ni * 8 + 2 * lc;
#pragma unroll
            for (int half = 0; half < 2; half++) {
                int gr = r0 + half * 8;
                if (gr >= M) continue;
                float v0 = acc[mi][ni][half * 2 + 0];
                float v1 = acc[mi][ni][half * 2 + 1];
                if (c0 < N) {
                    float o = v0 + (bias ? bias[c0] : 0.f);
                    C[(size_t)gr * N + c0] = o;
                }
                if (c0 + 1 < N) {
                    float o = v1 + (bias ? bias[c0 + 1] : 0.f);
                    C[(size_t)gr * N + c0 + 1] = o;
                }
            }
        }
    }
}

// ---------------- attention scores ----------------
__global__ void k_scores(const float* __restrict__ att_s, const float* __restrict__ att_d) {
    int n = blockIdx.x;
    int h = threadIdx.y;
    int lane = threadIdx.x;
    const float* hp = Hg + (size_t)n * HD + h * HID;
    const float* as = att_s + h * HID;
    const float* ad = att_d + h * HID;
    float s1 = 0.f, s2 = 0.f;
    for (int d = lane; d < HID; d += 32) {
        float v = hp[d];
        s1 += v * as[d];
        s2 += v * ad[d];
    }
#pragma unroll
    for (int o = 16; o; o >>= 1) {
        s1 += __shfl_down_sync(0xffffffffu, s1, o);
        s2 += __shfl_down_sync(0xffffffffu, s2, o);
    }
    if (lane == 0) {
        ASRCg[n * HEADS + h] = s1;
        ADSTg[n * HEADS + h] = s2;
    }
}

// ---------------- CSR build (by dst) ----------------
__global__ void k_zero_deg() {
    int i = blockIdx.x * blockDim.x + threadIdx.x;
    if (i < NN) DEGg[i] = 0;
}
__global__ void k_hist(const int* __restrict__ ei) {
    int e = blockIdx.x * blockDim.x + threadIdx.x;
    if (e < EE) atomicAdd(&DEGg[ei[EE + e]], 1);
}
__global__ void k_scan() {  // single block, 1024 threads; also writes CURg = rowptr[i]
    __shared__ int sh[1024];
    __shared__ int carry;
    int tid = threadIdx.x;
    if (tid == 0) carry = 0;
    __syncthreads();
    for (int base = 0; base < NN; base += 1024) {
        int i = base + tid;
        int v = (i < NN) ? DEGg[i] : 0;
        sh[tid] = v;
        __syncthreads();
        for (int off = 1; off < 1024; off <<= 1) {
            int t = (tid >= off) ? sh[tid - off] : 0;
            __syncthreads();
            sh[tid] += t;
            __syncthreads();
        }
        int c = carry;
        if (i < NN) {
            ROWPTRg[i + 1] = c + sh[tid];
            CURg[i] = c + sh[tid] - v;   // exclusive prefix = rowptr[i]
        }
        __syncthreads();
        if (tid == 1023) carry = c + sh[1023];
        __syncthreads();
    }
    if (tid == 0) ROWPTRg[0] = 0;
}
__global__ void k_fill(const int* __restrict__ ei) {
    int e = blockIdx.x * blockDim.x + threadIdx.x;
    if (e < EE) {
        int d = ei[EE + e];
        int p = atomicAdd(&CURg[d], 1);
        EIDXg[p] = e;
    }
}

// ---------------- fused softmax + pull aggregation + head-mean + bias + relu ------------
// Per dst node: pass1 segment-max over incoming edges (from ASRC/ADST, L2-resident);
// pass2 per chunk: w = exp(alpha - max) into smem (+den via smem atomics), then the
// feature gather consumes smem weights. out = (sum_h r_h/(den_h+1e-16))/4 + bias, relu.
__global__ __launch_bounds__(256) void k_aggregate(const int* __restrict__ ei,
                                                   const float* __restrict__ bias,
                                                   int layer2) {
    int n = blockIdx.x;
    int tid = threadIdx.x;
    int lane = tid & 31, wid = tid >> 5;
    int beg = ROWPTRg[n], end = ROWPTRg[n + 1];

    __shared__ float smax[4];
    __shared__ float sden[4];
    __shared__ float wmax[8][4];
    __shared__ float sw[4][256];
    __shared__ int   ssrc[256];

    float adst[4];
#pragma unroll
    for (int h = 0; h < 4; h++) adst[h] = ADSTg[n * 4 + h];

    // ---- pass 1: per-head max over edges ----
    float mx[4] = {-INFINITY, -INFINITY, -INFINITY, -INFINITY};
    for (int t = beg + tid; t < end; t += 256) {
        int e = EIDXg[t];
        int s = ei[e];
#pragma unroll
        for (int h = 0; h < 4; h++) {
            float a = ASRCg[s * 4 + h] + adst[h];
            a = (a > 0.f) ? a : 0.2f * a;
            mx[h] = fmaxf(mx[h], a);
        }
    }
#pragma unroll
    for (int h = 0; h < 4; h++)
#pragma unroll
        for (int o = 16; o; o >>= 1)
            mx[h] = fmaxf(mx[h], __shfl_down_sync(0xffffffffu, mx[h], o));
    if (lane == 0)
#pragma unroll
        for (int h = 0; h < 4; h++) wmax[wid][h] = mx[h];
    if (tid < 4) sden[tid] = 0.f;
    __syncthreads();
    if (tid == 0) {
#pragma unroll
        for (int h = 0; h < 4; h++) {
            float m = wmax[0][h];
#pragma unroll
            for (int w = 1; w < 8; w++) m = fmaxf(m, wmax[w][h]);
            smax[h] = m;
        }
    }
    __syncthreads();

    // ---- pass 2: chunks of 256 edges: weights to smem, then gather ----
    float r[3][4];
#pragma unroll
    for (int a = 0; a < 3; a++)
#pragma unroll
        for (int b = 0; b < 4; b++) r[a][b] = 0.f;

    for (int cs = beg; cs < end; cs += 256) {
        int cnt = min(256, end - cs);
        if (tid < cnt) {
            int e = EIDXg[cs + tid];
            int s = ei[e];
            ssrc[tid] = s;
#pragma unroll
            for (int h = 0; h < 4; h++) {
                float a = ASRCg[s * 4 + h] + adst[h];
                a = (a > 0.f) ? a : 0.2f * a;
                float w = expf(a - smax[h]);
                sw[h][tid] = w;
                atomicAdd(&sden[h], w);
            }
        }
        __syncthreads();
        for (int i = 0; i < cnt; i++) {
            const float* hp = Hg + (size_t)ssrc[i] * HD;
            float a0 = sw[0][i], a1 = sw[1][i], a2 = sw[2][i], a3 = sw[3][i];
#pragma unroll
            for (int jj = 0; jj < 3; jj++) {
                int j = tid + jj * 256;
                if (j < HID) {
                    r[jj][0] += hp[j] * a0;
                    r[jj][1] += hp[j + HID] * a1;
                    r[jj][2] += hp[j + 2 * HID] * a2;
                    r[jj][3] += hp[j + 3 * HID] * a3;
                }
            }
        }
        __syncthreads();
    }

    float dinv[4];
#pragma unroll
    for (int h = 0; h < 4; h++) dinv[h] = 1.f / (sden[h] + 1e-16f);

    float* xo = layer2 ? X2g : X1g;
#pragma unroll
    for (int jj = 0; jj < 3; jj++) {
        int j = tid + jj * 256;
        if (j < HID) {
            float v = (r[jj][0] * dinv[0] + r[jj][1] * dinv[1] +
                       r[jj][2] * dinv[2] + r[jj][3] * dinv[3]) * 0.25f + bias[j];
            v = v > 0.f ? v : 0.f;
            xo[(size_t)n * HID + j] = layer2 ? v : roundtf(v);
        }
    }
}

// ---------------- fused edge conv: (2x50 conv -> relu) -> (50 conv -> relu) ----------------
__global__ __launch_bounds__(128) void k_conv(const int* __restrict__ ei,
                                              const float* __restrict__ w4,
                                              const float* __restrict__ b4,
                                              const float* __restrict__ w6,
                                              const float* __restrict__ b6) {
    int e = blockIdx.x;
    __shared__ float xs[616], xd[616];
    __shared__ float y1[C1];
    __shared__ float c0[KER], c1[KER], c2[KER];
    int tid = threadIdx.x;
    int s = ei[e];
    int d = ei[EE + e];
    for (int j = tid; j < 616; j += 128) {
        xs[j] = (j < HID) ? X2g[(size_t)s * HID + j] : 0.f;
        xd[j] = (j < HID) ? X2g[(size_t)d * HID + j] : 0.f;
    }
    if (tid < KER) { c0[tid] = w4[tid]; c1[tid] = w4[KER + tid]; c2[tid] = w6[tid]; }
    __syncthreads();

    // conv1: 5 outputs/thread, register sliding window
    float bb4 = b4[0];
    int j0 = tid * 5;
    if (j0 < C1) {
        float acc[5] = {bb4, bb4, bb4, bb4, bb4};
        float ws[5], wd[5];
#pragma unroll
        for (int i = 0; i < 5; i++) { ws[i] = xs[j0 + i]; wd[i] = xd[j0 + i]; }
#pragma unroll
        for (int k = 0; k < KER; k++) {
            float u0 = c0[k], u1 = c1[k];
#pragma unroll
            for (int i = 0; i < 5; i++) acc[i] += ws[i] * u0 + wd[i] * u1;
            if (k < KER - 1) {
#pragma unroll
                for (int i = 0; i < 4; i++) { ws[i] = ws[i + 1]; wd[i] = wd[i + 1]; }
                ws[4] = xs[j0 + k + 5];
                wd[4] = xd[j0 + k + 5];
            }
        }
#pragma unroll
        for (int i = 0; i < 5; i++) {
            int j = j0 + i;
            if (j < C1) y1[j] = acc[i] > 0.f ? acc[i] : 0.f;
        }
    }
    __syncthreads();

    // conv2: 4 outputs/thread (128*4 = 512 exactly); output tf32-rounded for final GEMM
    float bb6 = b6[0];
    int j2 = tid * 4;
    float acc2[4] = {bb6, bb6, bb6, bb6};
    float wy[4];
#pragma unroll
    for (int i = 0; i < 4; i++) wy[i] = y1[j2 + i];
#pragma unroll
    for (int k = 0; k < KER; k++) {
        float u = c2[k];
#pragma unroll
        for (int i = 0; i < 4; i++) acc2[i] += wy[i] * u;
        if (k < KER - 1) {
#pragma unroll
            for (int i = 0; i < 3; i++) wy[i] = wy[i + 1];
            wy[3] = y1[j2 + k + 4];
        }
    }
    float4 o;
    o.x = roundtf(acc2[0] > 0.f ? acc2[0] : 0.f);
    o.y = roundtf(acc2[1] > 0.f ? acc2[1] : 0.f);
    o.z = roundtf(acc2[2] > 0.f ? acc2[2] : 0.f);
    o.w = roundtf(acc2[3] > 0.f ? acc2[3] : 0.f);
    *reinterpret_cast<float4*>(&Y2g[(size_t)e * C2 + j2]) = o;
}

// ---------------- host launcher ----------------
extern "C" void kernel_launch(void* const* d_in, const int* in_sizes, int n_in,
                              void* d_out, int out_size) {
    const float* x   = (const float*)d_in[0];
    const int*   ei  = (const int*)d_in[1];
    const float* w0  = (const float*)d_in[2];
    const float* b0  = (const float*)d_in[3];
    const float* as0 = (const float*)d_in[4];
    const float* ad0 = (const float*)d_in[5];
    const float* w2  = (const float*)d_in[6];
    const float* b2  = (const float*)d_in[7];
    const float* as1 = (const float*)d_in[8];
    const float* ad1 = (const float*)d_in[9];
    const float* w4  = (const float*)d_in[10];
    const float* b4  = (const float*)d_in[11];
    const float* w6  = (const float*)d_in[12];
    const float* b6  = (const float*)d_in[13];
    const float* w8  = (const float*)d_in[14];
    const float* b8  = (const float*)d_in[15];
    float* out = (float*)d_out;

    cudaFuncSetAttribute(k_gemm_tf32p, cudaFuncAttributeMaxDynamicSharedMemorySize, GEMM_SMEM);

    // --- pre-round GEMM operands to tf32 ---
    k_cvt<<<(NN * FIN + 255) / 256, 256>>>(x, NN * FIN, 0);
    k_cvt<<<(HD * FIN + 255) / 256, 256>>>(w0, HD * FIN, 1);
    k_cvt<<<(HD * HID + 255) / 256, 256>>>(w2, HD * HID, 2);
    k_cvt<<<(NOUT * C2 + 255) / 256, 256>>>(w8, NOUT * C2, 3);

    // --- CSR by dst (reused by both layers) ---
    k_zero_deg<<<(NN + 255) / 256, 256>>>();
    k_hist<<<(EE + 255) / 256, 256>>>(ei);
    k_scan<<<1, 1024>>>();
    k_fill<<<(EE + 255) / 256, 256>>>(ei);

    dim3 bScores(32, 4);
    dim3 gH((HD + 127) / 128, (NN + 127) / 128);

    // --- GAT layer 1 ---
    k_gemm_tf32p<<<gH, 256, GEMM_SMEM>>>(nullptr, nullptr, NN, HD, FIN, 0, 0, 0);
    k_scores<<<NN, bScores>>>(as0, ad0);
    k_aggregate<<<NN, 256>>>(ei, b0, 0);

    // --- GAT layer 2 ---
    k_gemm_tf32p<<<gH, 256, GEMM_SMEM>>>(nullptr, nullptr, NN, HD, HID, 1, 1, 0);
    k_scores<<<NN, bScores>>>(as1, ad1);
    k_aggregate<<<NN, 256>>>(ei, b2, 1);

    // --- fused edge convs ---
    k_conv<<<EE, 128>>>(ei, w4, b4, w6, b6);

    // --- final linear [E,512] x [512,86]^T + b8 ---
    dim3 gO((NOUT + 127) / 128, (EE + 127) / 128);
    k_gemm_tf32p<<<gO, 256, GEMM_SMEM>>>(b8, out, EE, NOUT, C2, 2, 2, 1);
}